// round 12
// baseline (speedup 1.0000x reference)
#include <cuda_runtime.h>
#include <cstdint>

#define NNODES 50000
#define NEDGES 600000
#define DIM 128
#define NREL 3

#define BM 128
#define BK 32
#define KTOT 512          // 128 (lin) + 3*128 (relations)
#define AS_STRIDE 133
#define WS_STRIDE 132

// ---------------- device scratch (no allocations allowed) -------------------
__device__ float g_hsum[NREL * NNODES * DIM];   // per-relation x-row sums / deg
__device__ int   g_cnt2[NNODES];                // histogram counts
__device__ int   g_off[NNODES + 1];             // CSR offsets
__device__ int   g_woff[NNODES];                // working offsets for fill
__device__ int   g_csr[NEDGES];                 // packed (rel<<16 | src)
__device__ float g_wcat[KTOT * DIM];            // [linT; W0; W1; W2] row-major [k][n]

// ---------------------------------------------------------------------------
__global__ void build_wcat(const float* __restrict__ lin_w,
                           const float* __restrict__ relw) {
    int k = blockIdx.x, j = threadIdx.x;
    float v;
    if (k < DIM) v = lin_w[j * DIM + k];
    else {
        int r = (k - DIM) >> 7, kk = (k - DIM) & 127;
        v = relw[r * DIM * DIM + kk * DIM + j];
    }
    g_wcat[k * DIM + j] = v;
}

__global__ void zero_cnt_kernel() {
    int i = blockIdx.x * blockDim.x + threadIdx.x;
    if (i < NNODES) g_cnt2[i] = 0;
}

__global__ void hist_kernel(const int* __restrict__ ei, int E) {
    int i = blockIdx.x * blockDim.x + threadIdx.x;
    if (i < E) atomicAdd(&g_cnt2[ei[E + i]], 1);
}

// Single-block exclusive scan over 50K counts.
__global__ void scan_kernel() {
    __shared__ int wsum[32];
    int t = threadIdx.x;
    const int CH = (NNODES + 1023) / 1024;   // 49
    int beg = t * CH, end = min(beg + CH, NNODES);
    int s = 0;
    for (int i = beg; i < end; i++) s += g_cnt2[i];

    int lane = t & 31, wid = t >> 5;
    int v = s;
    #pragma unroll
    for (int o = 1; o < 32; o <<= 1) {
        int n = __shfl_up_sync(0xffffffffu, v, o);
        if (lane >= o) v += n;
    }
    if (lane == 31) wsum[wid] = v;
    __syncthreads();
    if (wid == 0) {
        int w = wsum[lane];
        #pragma unroll
        for (int o = 1; o < 32; o <<= 1) {
            int n = __shfl_up_sync(0xffffffffu, w, o);
            if (lane >= o) w += n;
        }
        wsum[lane] = w;
    }
    __syncthreads();
    int excl = v - s + (wid > 0 ? wsum[wid - 1] : 0);
    int run = excl;
    for (int i = beg; i < end; i++) {
        g_off[i] = run;
        g_woff[i] = run;
        run += g_cnt2[i];
    }
    if (t == 1023) g_off[NNODES] = wsum[31];
}

__global__ void fill_kernel(const int* __restrict__ ei,
                            const int* __restrict__ et, int E) {
    int i = blockIdx.x * blockDim.x + threadIdx.x;
    if (i < E) {
        int d = ei[E + i];
        int r = min(max(et[i], 0), NREL - 1);
        int s = ei[i];
        int pos = atomicAdd(&g_woff[d], 1);
        g_csr[pos] = (r << 16) | s;
    }
}

// ---------------------------------------------------------------------------
// Warp per node: sum incoming x rows per relation, scale by 1/deg, store.
__global__ void __launch_bounds__(256) accum_kernel(const float* __restrict__ x) {
    int warp = threadIdx.x >> 5, lane = threadIdx.x & 31;
    int node = blockIdx.x * 8 + warp;
    if (node >= NNODES) return;
    int beg = g_off[node], end = g_off[node + 1];

    float4 a0 = make_float4(0.f, 0.f, 0.f, 0.f);
    float4 a1 = a0, a2 = a0;
    const float4* x4 = (const float4*)x;

    int i = beg;
    for (; i + 2 <= end; i += 2) {
        int p0 = g_csr[i], p1 = g_csr[i + 1];
        float4 v0 = x4[(p0 & 0xFFFF) * 32 + lane];
        float4 v1 = x4[(p1 & 0xFFFF) * 32 + lane];
        int r0 = p0 >> 16, r1 = p1 >> 16;
        if (r0 == 0)      { a0.x += v0.x; a0.y += v0.y; a0.z += v0.z; a0.w += v0.w; }
        else if (r0 == 1) { a1.x += v0.x; a1.y += v0.y; a1.z += v0.z; a1.w += v0.w; }
        else              { a2.x += v0.x; a2.y += v0.y; a2.z += v0.z; a2.w += v0.w; }
        if (r1 == 0)      { a0.x += v1.x; a0.y += v1.y; a0.z += v1.z; a0.w += v1.w; }
        else if (r1 == 1) { a1.x += v1.x; a1.y += v1.y; a1.z += v1.z; a1.w += v1.w; }
        else              { a2.x += v1.x; a2.y += v1.y; a2.z += v1.z; a2.w += v1.w; }
    }
    if (i < end) {
        int p0 = g_csr[i];
        float4 v0 = x4[(p0 & 0xFFFF) * 32 + lane];
        int r0 = p0 >> 16;
        if (r0 == 0)      { a0.x += v0.x; a0.y += v0.y; a0.z += v0.z; a0.w += v0.w; }
        else if (r0 == 1) { a1.x += v0.x; a1.y += v0.y; a1.z += v0.z; a1.w += v0.w; }
        else              { a2.x += v0.x; a2.y += v0.y; a2.z += v0.z; a2.w += v0.w; }
    }

    float inv = (end > beg) ? 1.0f / (float)(end - beg) : 1.0f;
    a0.x *= inv; a0.y *= inv; a0.z *= inv; a0.w *= inv;
    a1.x *= inv; a1.y *= inv; a1.z *= inv; a1.w *= inv;
    a2.x *= inv; a2.y *= inv; a2.z *= inv; a2.w *= inv;
    *(float4*)(g_hsum + ((size_t)0 * NNODES + node) * DIM + lane * 4) = a0;
    *(float4*)(g_hsum + ((size_t)1 * NNODES + node) * DIM + lane * 4) = a1;
    *(float4*)(g_hsum + ((size_t)2 * NNODES + node) * DIM + lane * 4) = a2;
}

// ---------------------------------------------------------------------------
// Fused GEMM + LayerNorm. C[128 nodes][128 out] per block, 8x8 per thread.
// A[node, k] = k<128 ? x[node,k] : hsum_scaled[r][node, k%128].
__global__ __launch_bounds__(256, 2) void final_gemm_kernel(
        const float* __restrict__ x,
        const float* __restrict__ lin_b,
        const float* __restrict__ gamma,
        const float* __restrict__ beta,
        float* __restrict__ out, int N) {
    __shared__ float As[BK * AS_STRIDE];
    __shared__ float Ws[BK * WS_STRIDE];

    int tid = threadIdx.x;
    int tx = tid & 15, ty = tid >> 4;
    int node0 = blockIdx.x * BM;

    unsigned long long acc[8][4];
    #pragma unroll
    for (int m = 0; m < 8; m++)
        #pragma unroll
        for (int p = 0; p < 4; p++) acc[m][p] = 0ull;

    auto loadA = [&](int kc, float4* pa) {
        #pragma unroll
        for (int i = 0; i < 4; i++) {
            int idx = tid + 256 * i;
            int row = idx >> 3, kq = idx & 7;
            int node = node0 + row;
            float4 v = make_float4(0.f, 0.f, 0.f, 0.f);
            if (node < N) {
                int k = kc * BK + kq * 4;
                int seg = k >> 7, koff = k & 127;
                if (seg == 0)
                    v = *(const float4*)(x + (size_t)node * DIM + koff);
                else
                    v = *(const float4*)(g_hsum +
                        ((size_t)(seg - 1) * NNODES + node) * DIM + koff);
            }
            pa[i] = v;
        }
    };
    auto loadW = [&](int kc, float4* pw) {
        #pragma unroll
        for (int i = 0; i < 4; i++) {
            int idx = tid + 256 * i;
            int kk = idx >> 5, q = idx & 31;
            pw[i] = *(const float4*)(g_wcat + (size_t)(kc * BK + kk) * DIM + q * 4);
        }
    };

    float4 pa[4], pw[4];
    loadA(0, pa);
    loadW(0, pw);

    for (int kc = 0; kc < KTOT / BK; kc++) {
        #pragma unroll
        for (int i = 0; i < 4; i++) {
            int idx = tid + 256 * i;
            int row = idx >> 3, kq = idx & 7;
            As[(kq * 4 + 0) * AS_STRIDE + row] = pa[i].x;
            As[(kq * 4 + 1) * AS_STRIDE + row] = pa[i].y;
            As[(kq * 4 + 2) * AS_STRIDE + row] = pa[i].z;
            As[(kq * 4 + 3) * AS_STRIDE + row] = pa[i].w;
            int kk = idx >> 5, q = idx & 31;
            *(float4*)&Ws[kk * WS_STRIDE + q * 4] = pw[i];
        }
        __syncthreads();
        if (kc + 1 < KTOT / BK) { loadA(kc + 1, pa); loadW(kc + 1, pw); }

        #pragma unroll 4
        for (int k = 0; k < BK; k++) {
            const float* ar = &As[k * AS_STRIDE + ty * 8];
            const float* wr = &Ws[k * WS_STRIDE + tx * 8];
            ulonglong2 wA = *(const ulonglong2*)wr;
            ulonglong2 wB = *(const ulonglong2*)(wr + 4);
            #pragma unroll
            for (int m = 0; m < 8; m++) {
                float a = ar[m];
                unsigned long long a2;
                asm("mov.b64 %0, {%1,%1};" : "=l"(a2) : "f"(a));
                asm("fma.rn.f32x2 %0, %1, %2, %0;" : "+l"(acc[m][0]) : "l"(a2), "l"(wA.x));
                asm("fma.rn.f32x2 %0, %1, %2, %0;" : "+l"(acc[m][1]) : "l"(a2), "l"(wA.y));
                asm("fma.rn.f32x2 %0, %1, %2, %0;" : "+l"(acc[m][2]) : "l"(a2), "l"(wB.x));
                asm("fma.rn.f32x2 %0, %1, %2, %0;" : "+l"(acc[m][3]) : "l"(a2), "l"(wB.y));
            }
        }
        __syncthreads();
    }

    float4 b0  = *(const float4*)(lin_b + tx * 8);
    float4 b1  = *(const float4*)(lin_b + tx * 8 + 4);
    float4 g0  = *(const float4*)(gamma + tx * 8);
    float4 g1  = *(const float4*)(gamma + tx * 8 + 4);
    float4 be0 = *(const float4*)(beta + tx * 8);
    float4 be1 = *(const float4*)(beta + tx * 8 + 4);

    #pragma unroll
    for (int m = 0; m < 8; m++) {
        int node = node0 + ty * 8 + m;
        float c[8];
        asm("mov.b64 {%0,%1}, %2;" : "=f"(c[0]), "=f"(c[1]) : "l"(acc[m][0]));
        asm("mov.b64 {%0,%1}, %2;" : "=f"(c[2]), "=f"(c[3]) : "l"(acc[m][1]));
        asm("mov.b64 {%0,%1}, %2;" : "=f"(c[4]), "=f"(c[5]) : "l"(acc[m][2]));
        asm("mov.b64 {%0,%1}, %2;" : "=f"(c[6]), "=f"(c[7]) : "l"(acc[m][3]));
        c[0] += b0.x; c[1] += b0.y; c[2] += b0.z; c[3] += b0.w;
        c[4] += b1.x; c[5] += b1.y; c[6] += b1.z; c[7] += b1.w;

        float s = 0.f, q = 0.f;
        #pragma unroll
        for (int j = 0; j < 8; j++) { s += c[j]; q += c[j] * c[j]; }
        #pragma unroll
        for (int o = 8; o > 0; o >>= 1) {
            s += __shfl_xor_sync(0xffffffffu, s, o);
            q += __shfl_xor_sync(0xffffffffu, q, o);
        }
        float mu = s * (1.0f / DIM);
        float var = q * (1.0f / DIM) - mu * mu;
        float rs = rsqrtf(fmaxf(var, 0.f) + 1e-5f);

        if (node < N) {
            float4 o0, o1;
            o0.x = fmaf(g0.x * (c[0] - mu), rs, be0.x);
            o0.y = fmaf(g0.y * (c[1] - mu), rs, be0.y);
            o0.z = fmaf(g0.z * (c[2] - mu), rs, be0.z);
            o0.w = fmaf(g0.w * (c[3] - mu), rs, be0.w);
            o1.x = fmaf(g1.x * (c[4] - mu), rs, be1.x);
            o1.y = fmaf(g1.y * (c[5] - mu), rs, be1.y);
            o1.z = fmaf(g1.z * (c[6] - mu), rs, be1.z);
            o1.w = fmaf(g1.w * (c[7] - mu), rs, be1.w);
            *(float4*)(out + (size_t)node * DIM + tx * 8)     = o0;
            *(float4*)(out + (size_t)node * DIM + tx * 8 + 4) = o1;
        }
    }
}

// ---------------------------------------------------------------------------
extern "C" void kernel_launch(void* const* d_in, const int* in_sizes, int n_in,
                              void* d_out, int out_size) {
    const float* x     = (const float*)d_in[0];
    const int*   ei    = (const int*)d_in[1];
    const int*   et    = (const int*)d_in[2];
    const float* relw  = (const float*)d_in[3];
    const float* lin_w = (const float*)d_in[4];
    const float* lin_b = (const float*)d_in[5];
    const float* gamma = (const float*)d_in[6];
    const float* beta  = (const float*)d_in[7];
    float* out = (float*)d_out;

    int N = in_sizes[0] / DIM;
    int E = in_sizes[2];

    build_wcat<<<KTOT, DIM>>>(lin_w, relw);
    zero_cnt_kernel<<<(NNODES + 255) / 256, 256>>>();
    hist_kernel<<<(E + 255) / 256, 256>>>(ei, E);
    scan_kernel<<<1, 1024>>>();
    fill_kernel<<<(E + 255) / 256, 256>>>(ei, et, E);
    accum_kernel<<<(NNODES + 7) / 8, 256>>>(x);
    final_gemm_kernel<<<(N + BM - 1) / BM, 256>>>(x, lin_b, gamma, beta, out, N);
}

// round 15
// speedup vs baseline: 1.4457x; 1.4457x over previous
#include <cuda_runtime.h>
#include <cstdint>

#define NNODES 50000
#define NEDGES 600000
#define DIM 128
#define NREL 3

#define BM 128
#define BK 32
#define KTOT 512          // 128 (lin) + 3*128 (relations)
#define AS_STRIDE 133
#define WS_STRIDE 132
#define NBLK 196          // ceil(NNODES/256)

// ---------------- device scratch (no allocations allowed) -------------------
__device__ float g_hsum[NREL * NNODES * DIM];   // per-relation x-row sums / deg
__device__ int   g_cnt2[NNODES];
__device__ int   g_off[NNODES + 1];
__device__ int   g_woff[NNODES];
__device__ int   g_part[NBLK];
__device__ int   g_csr[NEDGES];                 // packed (rel<<16 | src)
__device__ float g_wcat[KTOT * DIM];            // [linT; W0; W1; W2] row-major [k][n]

// ---------------------------------------------------------------------------
__global__ void build_wcat(const float* __restrict__ lin_w,
                           const float* __restrict__ relw) {
    int k = blockIdx.x, j = threadIdx.x;
    float v;
    if (k < DIM) v = lin_w[j * DIM + k];
    else {
        int r = (k - DIM) >> 7, kk = (k - DIM) & 127;
        v = relw[r * DIM * DIM + kk * DIM + j];
    }
    g_wcat[k * DIM + j] = v;
}

__global__ void zero_cnt_kernel() {
    int i = blockIdx.x * blockDim.x + threadIdx.x;
    if (i < NNODES) g_cnt2[i] = 0;
}

__global__ void hist_kernel(const int* __restrict__ ei, int E) {
    int i = blockIdx.x * blockDim.x + threadIdx.x;
    if (i < E) atomicAdd(&g_cnt2[ei[E + i]], 1);
}

// --- hierarchical scan: block sums -> scan partials -> per-block scan -------
__global__ void blocksum_kernel() {
    int tid = threadIdx.x, lane = tid & 31, wid = tid >> 5;
    int i = blockIdx.x * 256 + tid;
    int v = (i < NNODES) ? g_cnt2[i] : 0;
    #pragma unroll
    for (int o = 16; o > 0; o >>= 1) v += __shfl_xor_sync(0xffffffffu, v, o);
    __shared__ int ws[8];
    if (lane == 0) ws[wid] = v;
    __syncthreads();
    if (tid == 0) {
        int s = 0;
        #pragma unroll
        for (int j = 0; j < 8; j++) s += ws[j];
        g_part[blockIdx.x] = s;
    }
}

__global__ void scanpart_kernel(int E) {
    int t = threadIdx.x, lane = t & 31, wid = t >> 5;
    int c = (t < NBLK) ? g_part[t] : 0;
    int v = c;
    #pragma unroll
    for (int o = 1; o < 32; o <<= 1) {
        int n = __shfl_up_sync(0xffffffffu, v, o);
        if (lane >= o) v += n;
    }
    __shared__ int ws[8];
    if (lane == 31) ws[wid] = v;
    __syncthreads();
    if (wid == 0 && lane < 8) {
        int w = ws[lane];
        #pragma unroll
        for (int o = 1; o < 8; o <<= 1) {
            int n = __shfl_up_sync(0xffu, w, o);
            if (lane >= o) w += n;
        }
        ws[lane] = w;
    }
    __syncthreads();
    int excl = v - c + (wid > 0 ? ws[wid - 1] : 0);
    if (t < NBLK) g_part[t] = excl;
    if (t == 0) g_off[NNODES] = E;
}

__global__ void scanfinal_kernel() {
    int tid = threadIdx.x, lane = tid & 31, wid = tid >> 5;
    int i = blockIdx.x * 256 + tid;
    int c = (i < NNODES) ? g_cnt2[i] : 0;
    int v = c;
    #pragma unroll
    for (int o = 1; o < 32; o <<= 1) {
        int n = __shfl_up_sync(0xffffffffu, v, o);
        if (lane >= o) v += n;
    }
    __shared__ int ws[8];
    if (lane == 31) ws[wid] = v;
    __syncthreads();
    if (wid == 0 && lane < 8) {
        int w = ws[lane];
        #pragma unroll
        for (int o = 1; o < 8; o <<= 1) {
            int n = __shfl_up_sync(0xffu, w, o);
            if (lane >= o) w += n;
        }
        ws[lane] = w;
    }
    __syncthreads();
    int excl = v - c + (wid > 0 ? ws[wid - 1] : 0) + g_part[blockIdx.x];
    if (i < NNODES) { g_off[i] = excl; g_woff[i] = excl; }
}

__global__ void fill_kernel(const int* __restrict__ ei,
                            const int* __restrict__ et, int E) {
    int i = blockIdx.x * blockDim.x + threadIdx.x;
    if (i < E) {
        int d = ei[E + i];
        int r = min(max(et[i], 0), NREL - 1);
        int s = ei[i];
        int pos = atomicAdd(&g_woff[d], 1);
        g_csr[pos] = (r << 16) | s;
    }
}

// ---------------------------------------------------------------------------
// Warp per node: coalesced CSR chunk loads + MLP=4 gather pipeline.
__global__ void __launch_bounds__(256) accum_kernel(const float* __restrict__ x) {
    int warp = threadIdx.x >> 5, lane = threadIdx.x & 31;
    int node = blockIdx.x * 8 + warp;
    if (node >= NNODES) return;
    int beg = g_off[node], end = g_off[node + 1];

    float4 a0 = make_float4(0.f, 0.f, 0.f, 0.f);
    float4 a1 = a0, a2 = a0;
    const float4* x4 = (const float4*)x;

    for (int base = beg; base < end; base += 32) {
        int m = min(32, end - base);
        int p = 0;
        if (lane < m) p = g_csr[base + lane];
        int j = 0;
        for (; j + 4 <= m; j += 4) {
            int p0 = __shfl_sync(0xffffffffu, p, j);
            int p1 = __shfl_sync(0xffffffffu, p, j + 1);
            int p2 = __shfl_sync(0xffffffffu, p, j + 2);
            int p3 = __shfl_sync(0xffffffffu, p, j + 3);
            float4 v0 = x4[(p0 & 0xFFFF) * 32 + lane];
            float4 v1 = x4[(p1 & 0xFFFF) * 32 + lane];
            float4 v2 = x4[(p2 & 0xFFFF) * 32 + lane];
            float4 v3 = x4[(p3 & 0xFFFF) * 32 + lane];
            int r0 = p0 >> 16, r1 = p1 >> 16, r2 = p2 >> 16, r3 = p3 >> 16;
            if (r0 == 0)      { a0.x += v0.x; a0.y += v0.y; a0.z += v0.z; a0.w += v0.w; }
            else if (r0 == 1) { a1.x += v0.x; a1.y += v0.y; a1.z += v0.z; a1.w += v0.w; }
            else              { a2.x += v0.x; a2.y += v0.y; a2.z += v0.z; a2.w += v0.w; }
            if (r1 == 0)      { a0.x += v1.x; a0.y += v1.y; a0.z += v1.z; a0.w += v1.w; }
            else if (r1 == 1) { a1.x += v1.x; a1.y += v1.y; a1.z += v1.z; a1.w += v1.w; }
            else              { a2.x += v1.x; a2.y += v1.y; a2.z += v1.z; a2.w += v1.w; }
            if (r2 == 0)      { a0.x += v2.x; a0.y += v2.y; a0.z += v2.z; a0.w += v2.w; }
            else if (r2 == 1) { a1.x += v2.x; a1.y += v2.y; a1.z += v2.z; a1.w += v2.w; }
            else              { a2.x += v2.x; a2.y += v2.y; a2.z += v2.z; a2.w += v2.w; }
            if (r3 == 0)      { a0.x += v3.x; a0.y += v3.y; a0.z += v3.z; a0.w += v3.w; }
            else if (r3 == 1) { a1.x += v3.x; a1.y += v3.y; a1.z += v3.z; a1.w += v3.w; }
            else              { a2.x += v3.x; a2.y += v3.y; a2.z += v3.z; a2.w += v3.w; }
        }
        for (; j < m; j++) {
            int p0 = __shfl_sync(0xffffffffu, p, j);
            float4 v0 = x4[(p0 & 0xFFFF) * 32 + lane];
            int r0 = p0 >> 16;
            if (r0 == 0)      { a0.x += v0.x; a0.y += v0.y; a0.z += v0.z; a0.w += v0.w; }
            else if (r0 == 1) { a1.x += v0.x; a1.y += v0.y; a1.z += v0.z; a1.w += v0.w; }
            else              { a2.x += v0.x; a2.y += v0.y; a2.z += v0.z; a2.w += v0.w; }
        }
    }

    float inv = (end > beg) ? 1.0f / (float)(end - beg) : 1.0f;
    a0.x *= inv; a0.y *= inv; a0.z *= inv; a0.w *= inv;
    a1.x *= inv; a1.y *= inv; a1.z *= inv; a1.w *= inv;
    a2.x *= inv; a2.y *= inv; a2.z *= inv; a2.w *= inv;
    *(float4*)(g_hsum + ((size_t)0 * NNODES + node) * DIM + lane * 4) = a0;
    *(float4*)(g_hsum + ((size_t)1 * NNODES + node) * DIM + lane * 4) = a1;
    *(float4*)(g_hsum + ((size_t)2 * NNODES + node) * DIM + lane * 4) = a2;
}

// ---------------------------------------------------------------------------
// Fused GEMM + LayerNorm. C[128 nodes][128 out] per block, 8x8 per thread.
__global__ __launch_bounds__(256, 2) void final_gemm_kernel(
        const float* __restrict__ x,
        const float* __restrict__ lin_b,
        const float* __restrict__ gamma,
        const float* __restrict__ beta,
        float* __restrict__ out, int N) {
    __shared__ float As[BK * AS_STRIDE];
    __shared__ float Ws[BK * WS_STRIDE];

    int tid = threadIdx.x;
    int tx = tid & 15, ty = tid >> 4;
    int node0 = blockIdx.x * BM;

    unsigned long long acc[8][4];
    #pragma unroll
    for (int m = 0; m < 8; m++)
        #pragma unroll
        for (int p = 0; p < 4; p++) acc[m][p] = 0ull;

    auto loadA = [&](int kc, float4* pa) {
        #pragma unroll
        for (int i = 0; i < 4; i++) {
            int idx = tid + 256 * i;
            int row = idx >> 3, kq = idx & 7;
            int node = node0 + row;
            float4 v = make_float4(0.f, 0.f, 0.f, 0.f);
            if (node < N) {
                int k = kc * BK + kq * 4;
                int seg = k >> 7, koff = k & 127;
                if (seg == 0)
                    v = *(const float4*)(x + (size_t)node * DIM + koff);
                else
                    v = *(const float4*)(g_hsum +
                        ((size_t)(seg - 1) * NNODES + node) * DIM + koff);
            }
            pa[i] = v;
        }
    };
    auto loadW = [&](int kc, float4* pw) {
        #pragma unroll
        for (int i = 0; i < 4; i++) {
            int idx = tid + 256 * i;
            int kk = idx >> 5, q = idx & 31;
            pw[i] = *(const float4*)(g_wcat + (size_t)(kc * BK + kk) * DIM + q * 4);
        }
    };

    float4 pa[4], pw[4];
    loadA(0, pa);
    loadW(0, pw);

    for (int kc = 0; kc < KTOT / BK; kc++) {
        #pragma unroll
        for (int i = 0; i < 4; i++) {
            int idx = tid + 256 * i;
            int row = idx >> 3, kq = idx & 7;
            As[(kq * 4 + 0) * AS_STRIDE + row] = pa[i].x;
            As[(kq * 4 + 1) * AS_STRIDE + row] = pa[i].y;
            As[(kq * 4 + 2) * AS_STRIDE + row] = pa[i].z;
            As[(kq * 4 + 3) * AS_STRIDE + row] = pa[i].w;
            int kk = idx >> 5, q = idx & 31;
            *(float4*)&Ws[kk * WS_STRIDE + q * 4] = pw[i];
        }
        __syncthreads();
        if (kc + 1 < KTOT / BK) { loadA(kc + 1, pa); loadW(kc + 1, pw); }

        #pragma unroll 4
        for (int k = 0; k < BK; k++) {
            const float* ar = &As[k * AS_STRIDE + ty * 8];
            const float* wr = &Ws[k * WS_STRIDE + tx * 8];
            ulonglong2 wA = *(const ulonglong2*)wr;
            ulonglong2 wB = *(const ulonglong2*)(wr + 4);
            #pragma unroll
            for (int m = 0; m < 8; m++) {
                float a = ar[m];
                unsigned long long a2;
                asm("mov.b64 %0, {%1,%1};" : "=l"(a2) : "f"(a));
                asm("fma.rn.f32x2 %0, %1, %2, %0;" : "+l"(acc[m][0]) : "l"(a2), "l"(wA.x));
                asm("fma.rn.f32x2 %0, %1, %2, %0;" : "+l"(acc[m][1]) : "l"(a2), "l"(wA.y));
                asm("fma.rn.f32x2 %0, %1, %2, %0;" : "+l"(acc[m][2]) : "l"(a2), "l"(wB.x));
                asm("fma.rn.f32x2 %0, %1, %2, %0;" : "+l"(acc[m][3]) : "l"(a2), "l"(wB.y));
            }
        }
        __syncthreads();
    }

    float4 b0  = *(const float4*)(lin_b + tx * 8);
    float4 b1  = *(const float4*)(lin_b + tx * 8 + 4);
    float4 g0  = *(const float4*)(gamma + tx * 8);
    float4 g1  = *(const float4*)(gamma + tx * 8 + 4);
    float4 be0 = *(const float4*)(beta + tx * 8);
    float4 be1 = *(const float4*)(beta + tx * 8 + 4);

    #pragma unroll
    for (int m = 0; m < 8; m++) {
        int node = node0 + ty * 8 + m;
        float c[8];
        asm("mov.b64 {%0,%1}, %2;" : "=f"(c[0]), "=f"(c[1]) : "l"(acc[m][0]));
        asm("mov.b64 {%0,%1}, %2;" : "=f"(c[2]), "=f"(c[3]) : "l"(acc[m][1]));
        asm("mov.b64 {%0,%1}, %2;" : "=f"(c[4]), "=f"(c[5]) : "l"(acc[m][2]));
        asm("mov.b64 {%0,%1}, %2;" : "=f"(c[6]), "=f"(c[7]) : "l"(acc[m][3]));
        c[0] += b0.x; c[1] += b0.y; c[2] += b0.z; c[3] += b0.w;
        c[4] += b1.x; c[5] += b1.y; c[6] += b1.z; c[7] += b1.w;

        float s = 0.f, q = 0.f;
        #pragma unroll
        for (int j = 0; j < 8; j++) { s += c[j]; q += c[j] * c[j]; }
        #pragma unroll
        for (int o = 8; o > 0; o >>= 1) {
            s += __shfl_xor_sync(0xffffffffu, s, o);
            q += __shfl_xor_sync(0xffffffffu, q, o);
        }
        float mu = s * (1.0f / DIM);
        float var = q * (1.0f / DIM) - mu * mu;
        float rs = rsqrtf(fmaxf(var, 0.f) + 1e-5f);

        if (node < N) {
            float4 o0, o1;
            o0.x = fmaf(g0.x * (c[0] - mu), rs, be0.x);
            o0.y = fmaf(g0.y * (c[1] - mu), rs, be0.y);
            o0.z = fmaf(g0.z * (c[2] - mu), rs, be0.z);
            o0.w = fmaf(g0.w * (c[3] - mu), rs, be0.w);
            o1.x = fmaf(g1.x * (c[4] - mu), rs, be1.x);
            o1.y = fmaf(g1.y * (c[5] - mu), rs, be1.y);
            o1.z = fmaf(g1.z * (c[6] - mu), rs, be1.z);
            o1.w = fmaf(g1.w * (c[7] - mu), rs, be1.w);
            *(float4*)(out + (size_t)node * DIM + tx * 8)     = o0;
            *(float4*)(out + (size_t)node * DIM + tx * 8 + 4) = o1;
        }
    }
}

// ---------------------------------------------------------------------------
extern "C" void kernel_launch(void* const* d_in, const int* in_sizes, int n_in,
                              void* d_out, int out_size) {
    const float* x     = (const float*)d_in[0];
    const int*   ei    = (const int*)d_in[1];
    const int*   et    = (const int*)d_in[2];
    const float* relw  = (const float*)d_in[3];
    const float* lin_w = (const float*)d_in[4];
    const float* lin_b = (const float*)d_in[5];
    const float* gamma = (const float*)d_in[6];
    const float* beta  = (const float*)d_in[7];
    float* out = (float*)d_out;

    int N = in_sizes[0] / DIM;
    int E = in_sizes[2];

    build_wcat<<<KTOT, DIM>>>(lin_w, relw);
    zero_cnt_kernel<<<NBLK, 256>>>();
    hist_kernel<<<(E + 255) / 256, 256>>>(ei, E);
    blocksum_kernel<<<NBLK, 256>>>();
    scanpart_kernel<<<1, 256>>>(E);
    scanfinal_kernel<<<NBLK, 256>>>();
    fill_kernel<<<(E + 255) / 256, 256>>>(ei, et, E);
    accum_kernel<<<(NNODES + 7) / 8, 256>>>(x);
    final_gemm_kernel<<<(N + BM - 1) / BM, 256>>>(x, lin_b, gamma, beta, out, N);
}

// round 16
// speedup vs baseline: 2.0461x; 1.4153x over previous
#include <cuda_runtime.h>
#include <cuda_bf16.h>
#include <cstdint>

#define NNODES 50000
#define NEDGES 600000
#define DIM 128
#define NREL 3

#define BM 128
#define KTOT 512          // 128 (lin) + 3*128 (relations)
#define NBLK 196          // ceil(NNODES/256)

// smem byte offsets for the GEMM kernel: A/B bf16 chunks [128][72] (144B rows)
#define ROWB 144
#define OFF_AHI 0
#define OFF_ALO 18432
#define OFF_BHI 36864
#define OFF_BLO 55296
#define SMEM_TOT 73728

// ---------------- device scratch (no allocations allowed) -------------------
__device__ float g_hsum[NREL * NNODES * DIM];
__device__ int   g_cnt2[NNODES];
__device__ int   g_off[NNODES + 1];
__device__ int   g_woff[NNODES];
__device__ int   g_part[NBLK];
__device__ int   g_csr[NEDGES];
__device__ __nv_bfloat16 g_wThi[DIM * KTOT];   // wT[n][k] hi
__device__ __nv_bfloat16 g_wTlo[DIM * KTOT];   // wT[n][k] lo

// ---------------------------------------------------------------------------
__device__ __forceinline__ void split2(float a, float b, uint32_t& hi, uint32_t& lo) {
    __nv_bfloat16 h0 = __float2bfloat16(a), h1 = __float2bfloat16(b);
    __nv_bfloat16 l0 = __float2bfloat16(a - __bfloat162float(h0));
    __nv_bfloat16 l1 = __float2bfloat16(b - __bfloat162float(h1));
    hi = (uint32_t)*(unsigned short*)&h0 | ((uint32_t)*(unsigned short*)&h1 << 16);
    lo = (uint32_t)*(unsigned short*)&l0 | ((uint32_t)*(unsigned short*)&l1 << 16);
}

#define MMA_BF16(d, a, b)                                                     \
    asm volatile("mma.sync.aligned.m16n8k16.row.col.f32.bf16.bf16.f32 "       \
        "{%0,%1,%2,%3}, {%4,%5,%6,%7}, {%8,%9}, {%0,%1,%2,%3};"               \
        : "+f"((d)[0]), "+f"((d)[1]), "+f"((d)[2]), "+f"((d)[3])              \
        : "r"((a)[0]), "r"((a)[1]), "r"((a)[2]), "r"((a)[3]),                 \
          "r"((b)[0]), "r"((b)[1]))

// ---------------------------------------------------------------------------
// wT[n][k] = Wcat[k][n], split to bf16 hi/lo.
__global__ void build_wT(const float* __restrict__ lin_w,
                         const float* __restrict__ relw) {
    int n = blockIdx.x, k = threadIdx.x;
    float v;
    if (k < DIM) v = lin_w[n * DIM + k];
    else {
        int r = (k - DIM) >> 7, kk = (k - DIM) & 127;
        v = relw[r * DIM * DIM + kk * DIM + n];
    }
    __nv_bfloat16 h = __float2bfloat16(v);
    __nv_bfloat16 l = __float2bfloat16(v - __bfloat162float(h));
    g_wThi[n * KTOT + k] = h;
    g_wTlo[n * KTOT + k] = l;
}

__global__ void zero_cnt_kernel() {
    int i = blockIdx.x * blockDim.x + threadIdx.x;
    if (i < NNODES) g_cnt2[i] = 0;
}

__global__ void hist_kernel(const int* __restrict__ ei, int E) {
    int i = blockIdx.x * blockDim.x + threadIdx.x;
    if (i < E) atomicAdd(&g_cnt2[ei[E + i]], 1);
}

__global__ void blocksum_kernel() {
    int tid = threadIdx.x, lane = tid & 31, wid = tid >> 5;
    int i = blockIdx.x * 256 + tid;
    int v = (i < NNODES) ? g_cnt2[i] : 0;
    #pragma unroll
    for (int o = 16; o > 0; o >>= 1) v += __shfl_xor_sync(0xffffffffu, v, o);
    __shared__ int ws[8];
    if (lane == 0) ws[wid] = v;
    __syncthreads();
    if (tid == 0) {
        int s = 0;
        #pragma unroll
        for (int j = 0; j < 8; j++) s += ws[j];
        g_part[blockIdx.x] = s;
    }
}

__global__ void scanpart_kernel(int E) {
    int t = threadIdx.x, lane = t & 31, wid = t >> 5;
    int c = (t < NBLK) ? g_part[t] : 0;
    int v = c;
    #pragma unroll
    for (int o = 1; o < 32; o <<= 1) {
        int n = __shfl_up_sync(0xffffffffu, v, o);
        if (lane >= o) v += n;
    }
    __shared__ int ws[8];
    if (lane == 31) ws[wid] = v;
    __syncthreads();
    if (wid == 0 && lane < 8) {
        int w = ws[lane];
        #pragma unroll
        for (int o = 1; o < 8; o <<= 1) {
            int n = __shfl_up_sync(0xffu, w, o);
            if (lane >= o) w += n;
        }
        ws[lane] = w;
    }
    __syncthreads();
    int excl = v - c + (wid > 0 ? ws[wid - 1] : 0);
    if (t < NBLK) g_part[t] = excl;
    if (t == 0) g_off[NNODES] = E;
}

__global__ void scanfinal_kernel() {
    int tid = threadIdx.x, lane = tid & 31, wid = tid >> 5;
    int i = blockIdx.x * 256 + tid;
    int c = (i < NNODES) ? g_cnt2[i] : 0;
    int v = c;
    #pragma unroll
    for (int o = 1; o < 32; o <<= 1) {
        int n = __shfl_up_sync(0xffffffffu, v, o);
        if (lane >= o) v += n;
    }
    __shared__ int ws[8];
    if (lane == 31) ws[wid] = v;
    __syncthreads();
    if (wid == 0 && lane < 8) {
        int w = ws[lane];
        #pragma unroll
        for (int o = 1; o < 8; o <<= 1) {
            int n = __shfl_up_sync(0xffu, w, o);
            if (lane >= o) w += n;
        }
        ws[lane] = w;
    }
    __syncthreads();
    int excl = v - c + (wid > 0 ? ws[wid - 1] : 0) + g_part[blockIdx.x];
    if (i < NNODES) { g_off[i] = excl; g_woff[i] = excl; }
}

__global__ void fill_kernel(const int* __restrict__ ei,
                            const int* __restrict__ et, int E) {
    int i = blockIdx.x * blockDim.x + threadIdx.x;
    if (i < E) {
        int d = ei[E + i];
        int r = min(max(et[i], 0), NREL - 1);
        int s = ei[i];
        int pos = atomicAdd(&g_woff[d], 1);
        g_csr[pos] = (r << 16) | s;
    }
}

// ---------------------------------------------------------------------------
// Warp per node: coalesced CSR chunk loads + MLP=4 gather pipeline.
__global__ void __launch_bounds__(256) accum_kernel(const float* __restrict__ x) {
    int warp = threadIdx.x >> 5, lane = threadIdx.x & 31;
    int node = blockIdx.x * 8 + warp;
    if (node >= NNODES) return;
    int beg = g_off[node], end = g_off[node + 1];

    float4 a0 = make_float4(0.f, 0.f, 0.f, 0.f);
    float4 a1 = a0, a2 = a0;
    const float4* x4 = (const float4*)x;

    for (int base = beg; base < end; base += 32) {
        int m = min(32, end - base);
        int p = 0;
        if (lane < m) p = g_csr[base + lane];
        int j = 0;
        for (; j + 4 <= m; j += 4) {
            int p0 = __shfl_sync(0xffffffffu, p, j);
            int p1 = __shfl_sync(0xffffffffu, p, j + 1);
            int p2 = __shfl_sync(0xffffffffu, p, j + 2);
            int p3 = __shfl_sync(0xffffffffu, p, j + 3);
            float4 v0 = x4[(p0 & 0xFFFF) * 32 + lane];
            float4 v1 = x4[(p1 & 0xFFFF) * 32 + lane];
            float4 v2 = x4[(p2 & 0xFFFF) * 32 + lane];
            float4 v3 = x4[(p3 & 0xFFFF) * 32 + lane];
            int r0 = p0 >> 16, r1 = p1 >> 16, r2 = p2 >> 16, r3 = p3 >> 16;
            if (r0 == 0)      { a0.x += v0.x; a0.y += v0.y; a0.z += v0.z; a0.w += v0.w; }
            else if (r0 == 1) { a1.x += v0.x; a1.y += v0.y; a1.z += v0.z; a1.w += v0.w; }
            else              { a2.x += v0.x; a2.y += v0.y; a2.z += v0.z; a2.w += v0.w; }
            if (r1 == 0)      { a0.x += v1.x; a0.y += v1.y; a0.z += v1.z; a0.w += v1.w; }
            else if (r1 == 1) { a1.x += v1.x; a1.y += v1.y; a1.z += v1.z; a1.w += v1.w; }
            else              { a2.x += v1.x; a2.y += v1.y; a2.z += v1.z; a2.w += v1.w; }
            if (r2 == 0)      { a0.x += v2.x; a0.y += v2.y; a0.z += v2.z; a0.w += v2.w; }
            else if (r2 == 1) { a1.x += v2.x; a1.y += v2.y; a1.z += v2.z; a1.w += v2.w; }
            else              { a2.x += v2.x; a2.y += v2.y; a2.z += v2.z; a2.w += v2.w; }
            if (r3 == 0)      { a0.x += v3.x; a0.y += v3.y; a0.z += v3.z; a0.w += v3.w; }
            else if (r3 == 1) { a1.x += v3.x; a1.y += v3.y; a1.z += v3.z; a1.w += v3.w; }
            else              { a2.x += v3.x; a2.y += v3.y; a2.z += v3.z; a2.w += v3.w; }
        }
        for (; j < m; j++) {
            int p0 = __shfl_sync(0xffffffffu, p, j);
            float4 v0 = x4[(p0 & 0xFFFF) * 32 + lane];
            int r0 = p0 >> 16;
            if (r0 == 0)      { a0.x += v0.x; a0.y += v0.y; a0.z += v0.z; a0.w += v0.w; }
            else if (r0 == 1) { a1.x += v0.x; a1.y += v0.y; a1.z += v0.z; a1.w += v0.w; }
            else              { a2.x += v0.x; a2.y += v0.y; a2.z += v0.z; a2.w += v0.w; }
        }
    }

    float inv = (end > beg) ? 1.0f / (float)(end - beg) : 1.0f;
    a0.x *= inv; a0.y *= inv; a0.z *= inv; a0.w *= inv;
    a1.x *= inv; a1.y *= inv; a1.z *= inv; a1.w *= inv;
    a2.x *= inv; a2.y *= inv; a2.z *= inv; a2.w *= inv;
    *(float4*)(g_hsum + ((size_t)0 * NNODES + node) * DIM + lane * 4) = a0;
    *(float4*)(g_hsum + ((size_t)1 * NNODES + node) * DIM + lane * 4) = a1;
    *(float4*)(g_hsum + ((size_t)2 * NNODES + node) * DIM + lane * 4) = a2;
}

// ---------------------------------------------------------------------------
// Fused GEMM (bf16 3-split mma.sync) + LayerNorm.
// Warp grid 4(m)x2(n): warp tile M=32, N=64. K chunks of 64.
__global__ __launch_bounds__(256) void final_gemm_mma(
        const float* __restrict__ x,
        const float* __restrict__ lin_b,
        const float* __restrict__ gamma,
        const float* __restrict__ beta,
        float* __restrict__ out, int N) {
    extern __shared__ char smem[];
    int tid = threadIdx.x, lane = tid & 31, wid = tid >> 5;
    int wm = wid >> 1, wn = wid & 1;
    int node0 = blockIdx.x * BM;
    int r = lane >> 2, q = lane & 3;

    float acc[2][8][4];
    #pragma unroll
    for (int mi = 0; mi < 2; mi++)
        #pragma unroll
        for (int ni = 0; ni < 8; ni++)
            #pragma unroll
            for (int j = 0; j < 4; j++) acc[mi][ni][j] = 0.f;

    for (int kc = 0; kc < KTOT / 64; kc++) {
        int k0 = kc * 64;
        int seg = k0 >> 7;
        int koff = k0 & 127;

        // stage A: 128 rows x 64 k fp32 -> bf16 hi/lo smem
        #pragma unroll
        for (int i = 0; i < 8; i++) {
            int f = i * 256 + tid;
            int row = f >> 4, fc = f & 15;
            int node = node0 + row;
            float4 v = make_float4(0.f, 0.f, 0.f, 0.f);
            if (node < N) {
                const float* basep = (seg == 0)
                    ? x + (size_t)node * DIM
                    : g_hsum + ((size_t)(seg - 1) * NNODES + node) * DIM;
                v = *(const float4*)(basep + koff + fc * 4);
            }
            uint32_t h01, l01, h23, l23;
            split2(v.x, v.y, h01, l01);
            split2(v.z, v.w, h23, l23);
            char* pa = smem + OFF_AHI + row * ROWB + fc * 8;
            char* pl = smem + OFF_ALO + row * ROWB + fc * 8;
            *(uint32_t*)(pa) = h01; *(uint32_t*)(pa + 4) = h23;
            *(uint32_t*)(pl) = l01; *(uint32_t*)(pl + 4) = l23;
        }
        // stage B: 128 n-rows x 64 k bf16 (pre-split)
        #pragma unroll
        for (int i = 0; i < 4; i++) {
            int idx = i * 256 + tid;
            int n = idx >> 3, g = idx & 7;
            *(int4*)(smem + OFF_BHI + n * ROWB + g * 16) =
                *(const int4*)(g_wThi + (size_t)n * KTOT + k0 + g * 8);
            *(int4*)(smem + OFF_BLO + n * ROWB + g * 16) =
                *(const int4*)(g_wTlo + (size_t)n * KTOT + k0 + g * 8);
        }
        __syncthreads();

        #pragma unroll
        for (int k16 = 0; k16 < 4; k16++) {
            int kb = k16 * 16 + q * 2;
            uint32_t ah[2][4], al[2][4];
            #pragma unroll
            for (int mi = 0; mi < 2; mi++) {
                int rb = wm * 32 + mi * 16 + r;
                const char* ph = smem + OFF_AHI;
                const char* pl = smem + OFF_ALO;
                ah[mi][0] = *(const uint32_t*)(ph + rb * ROWB + kb * 2);
                ah[mi][1] = *(const uint32_t*)(ph + (rb + 8) * ROWB + kb * 2);
                ah[mi][2] = *(const uint32_t*)(ph + rb * ROWB + (kb + 8) * 2);
                ah[mi][3] = *(const uint32_t*)(ph + (rb + 8) * ROWB + (kb + 8) * 2);
                al[mi][0] = *(const uint32_t*)(pl + rb * ROWB + kb * 2);
                al[mi][1] = *(const uint32_t*)(pl + (rb + 8) * ROWB + kb * 2);
                al[mi][2] = *(const uint32_t*)(pl + rb * ROWB + (kb + 8) * 2);
                al[mi][3] = *(const uint32_t*)(pl + (rb + 8) * ROWB + (kb + 8) * 2);
            }
            uint32_t bh[8][2], bl[8][2];
            #pragma unroll
            for (int ni = 0; ni < 8; ni++) {
                int n = wn * 64 + ni * 8 + r;
                bh[ni][0] = *(const uint32_t*)(smem + OFF_BHI + n * ROWB + kb * 2);
                bh[ni][1] = *(const uint32_t*)(smem + OFF_BHI + n * ROWB + (kb + 8) * 2);
                bl[ni][0] = *(const uint32_t*)(smem + OFF_BLO + n * ROWB + kb * 2);
                bl[ni][1] = *(const uint32_t*)(smem + OFF_BLO + n * ROWB + (kb + 8) * 2);
            }
            #pragma unroll
            for (int mi = 0; mi < 2; mi++)
                #pragma unroll
                for (int ni = 0; ni < 8; ni++) {
                    MMA_BF16(acc[mi][ni], ah[mi], bh[ni]);
                    MMA_BF16(acc[mi][ni], ah[mi], bl[ni]);
                    MMA_BF16(acc[mi][ni], al[mi], bh[ni]);
                }
        }
        __syncthreads();
    }

    // ---- bias + LayerNorm (cross-warp partials in smem) ----
    float* sS = (float*)smem;          // [2][128]
    float* sQ = ((float*)smem) + 256;  // [2][128]

    #pragma unroll
    for (int mi = 0; mi < 2; mi++) {
        #pragma unroll
        for (int ni = 0; ni < 8; ni++) {
            int col = wn * 64 + ni * 8 + q * 2;
            float2 bb = *(const float2*)(lin_b + col);
            acc[mi][ni][0] += bb.x; acc[mi][ni][1] += bb.y;
            acc[mi][ni][2] += bb.x; acc[mi][ni][3] += bb.y;
        }
        float sa = 0.f, qa = 0.f, sb = 0.f, qb = 0.f;
        #pragma unroll
        for (int ni = 0; ni < 8; ni++) {
            float c0 = acc[mi][ni][0], c1 = acc[mi][ni][1];
            float c2 = acc[mi][ni][2], c3 = acc[mi][ni][3];
            sa += c0 + c1; qa += c0 * c0 + c1 * c1;
            sb += c2 + c3; qb += c2 * c2 + c3 * c3;
        }
        #pragma unroll
        for (int o = 1; o <= 2; o <<= 1) {
            sa += __shfl_xor_sync(0xffffffffu, sa, o);
            qa += __shfl_xor_sync(0xffffffffu, qa, o);
            sb += __shfl_xor_sync(0xffffffffu, sb, o);
            qb += __shfl_xor_sync(0xffffffffu, qb, o);
        }
        if (q == 0) {
            int ra = wm * 32 + mi * 16 + r;
            sS[wn * 128 + ra] = sa;     sQ[wn * 128 + ra] = qa;
            sS[wn * 128 + ra + 8] = sb; sQ[wn * 128 + ra + 8] = qb;
        }
    }
    __syncthreads();

    #pragma unroll
    for (int mi = 0; mi < 2; mi++) {
        int ra = wm * 32 + mi * 16 + r;
        float s_a = sS[ra] + sS[128 + ra];
        float q_a = sQ[ra] + sQ[128 + ra];
        float s_b = sS[ra + 8] + sS[128 + ra + 8];
        float q_b = sQ[ra + 8] + sQ[128 + ra + 8];
        float mu_a = s_a * (1.0f / DIM);
        float mu_b = s_b * (1.0f / DIM);
        float rs_a = rsqrtf(fmaxf(q_a * (1.0f / DIM) - mu_a * mu_a, 0.f) + 1e-5f);
        float rs_b = rsqrtf(fmaxf(q_b * (1.0f / DIM) - mu_b * mu_b, 0.f) + 1e-5f);
        int na = node0 + ra, nb = na + 8;
        #pragma unroll
        for (int ni = 0; ni < 8; ni++) {
            int col = wn * 64 + ni * 8 + q * 2;
            float2 gm = *(const float2*)(gamma + col);
            float2 be = *(const float2*)(beta + col);
            if (na < N) {
                float2 o0;
                o0.x = fmaf(gm.x * (acc[mi][ni][0] - mu_a), rs_a, be.x);
                o0.y = fmaf(gm.y * (acc[mi][ni][1] - mu_a), rs_a, be.y);
                *(float2*)(out + (size_t)na * DIM + col) = o0;
            }
            if (nb < N) {
                float2 o1;
                o1.x = fmaf(gm.x * (acc[mi][ni][2] - mu_b), rs_b, be.x);
                o1.y = fmaf(gm.y * (acc[mi][ni][3] - mu_b), rs_b, be.y);
                *(float2*)(out + (size_t)nb * DIM + col) = o1;
            }
        }
    }
}

// ---------------------------------------------------------------------------
extern "C" void kernel_launch(void* const* d_in, const int* in_sizes, int n_in,
                              void* d_out, int out_size) {
    const float* x     = (const float*)d_in[0];
    const int*   ei    = (const int*)d_in[1];
    const int*   et    = (const int*)d_in[2];
    const float* relw  = (const float*)d_in[3];
    const float* lin_w = (const float*)d_in[4];
    const float* lin_b = (const float*)d_in[5];
    const float* gamma = (const float*)d_in[6];
    const float* beta  = (const float*)d_in[7];
    float* out = (float*)d_out;

    int N = in_sizes[0] / DIM;
    int E = in_sizes[2];

    cudaFuncSetAttribute(final_gemm_mma,
                         cudaFuncAttributeMaxDynamicSharedMemorySize, SMEM_TOT);

    build_wT<<<DIM, KTOT>>>(lin_w, relw);
    zero_cnt_kernel<<<NBLK, 256>>>();
    hist_kernel<<<(E + 255) / 256, 256>>>(ei, E);
    blocksum_kernel<<<NBLK, 256>>>();
    scanpart_kernel<<<1, 256>>>(E);
    scanfinal_kernel<<<NBLK, 256>>>();
    fill_kernel<<<(E + 255) / 256, 256>>>(ei, et, E);
    accum_kernel<<<(NNODES + 7) / 8, 256>>>(x);
    final_gemm_mma<<<(N + BM - 1) / BM, 256, SMEM_TOT>>>(x, lin_b, gamma, beta, out, N);
}

// round 17
// speedup vs baseline: 2.1958x; 1.0732x over previous
#include <cuda_runtime.h>
#include <cuda_bf16.h>
#include <cstdint>

#define NNODES 50000
#define NEDGES 600000
#define DIM 128
#define NREL 3

#define BM 128
#define KTOT 512          // 128 (lin) + 3*128 (relations)
#define NBLK 196          // ceil(NNODES/256)

// smem byte offsets for the GEMM kernel: A/B bf16 chunks [128][72] (144B rows)
#define ROWB 144
#define OFF_AHI 0
#define OFF_ALO 18432
#define OFF_BHI 36864
#define OFF_BLO 55296
#define SMEM_TOT 73728

// ---------------- device scratch (no allocations allowed) -------------------
__device__ int   g_cnt2[NNODES];
__device__ int   g_off[NNODES + 1];
__device__ int   g_woff[NNODES];
__device__ int   g_part[NBLK];
__device__ int   g_csr[NEDGES];
__device__ __nv_bfloat16 g_wThi[DIM * KTOT];       // wT[n][k] hi
__device__ __nv_bfloat16 g_wTlo[DIM * KTOT];       // wT[n][k] lo
// Pre-split A image: [seg 0..3][node][128] bf16  (seg0 = x, seg1..3 = hsum_r/deg)
__device__ __nv_bfloat16 g_Ahi[4 * NNODES * DIM];
__device__ __nv_bfloat16 g_Alo[4 * NNODES * DIM];

// ---------------------------------------------------------------------------
__device__ __forceinline__ void split4(float4 v, uint2& hi, uint2& lo) {
    __nv_bfloat16 h0 = __float2bfloat16(v.x), h1 = __float2bfloat16(v.y);
    __nv_bfloat16 h2 = __float2bfloat16(v.z), h3 = __float2bfloat16(v.w);
    __nv_bfloat16 l0 = __float2bfloat16(v.x - __bfloat162float(h0));
    __nv_bfloat16 l1 = __float2bfloat16(v.y - __bfloat162float(h1));
    __nv_bfloat16 l2 = __float2bfloat16(v.z - __bfloat162float(h2));
    __nv_bfloat16 l3 = __float2bfloat16(v.w - __bfloat162float(h3));
    hi.x = (uint32_t)*(unsigned short*)&h0 | ((uint32_t)*(unsigned short*)&h1 << 16);
    hi.y = (uint32_t)*(unsigned short*)&h2 | ((uint32_t)*(unsigned short*)&h3 << 16);
    lo.x = (uint32_t)*(unsigned short*)&l0 | ((uint32_t)*(unsigned short*)&l1 << 16);
    lo.y = (uint32_t)*(unsigned short*)&l2 | ((uint32_t)*(unsigned short*)&l3 << 16);
}

#define MMA_BF16(d, a, b)                                                     \
    asm volatile("mma.sync.aligned.m16n8k16.row.col.f32.bf16.bf16.f32 "       \
        "{%0,%1,%2,%3}, {%4,%5,%6,%7}, {%8,%9}, {%0,%1,%2,%3};"               \
        : "+f"((d)[0]), "+f"((d)[1]), "+f"((d)[2]), "+f"((d)[3])              \
        : "r"((a)[0]), "r"((a)[1]), "r"((a)[2]), "r"((a)[3]),                 \
          "r"((b)[0]), "r"((b)[1]))

// ---------------------------------------------------------------------------
// prep: build wT hi/lo split  +  zero histogram counts (grid-stride).
__global__ void prep_kernel(const float* __restrict__ lin_w,
                            const float* __restrict__ relw) {
    int idx = blockIdx.x * blockDim.x + threadIdx.x;
    if (idx < DIM * KTOT) {
        int n = idx / KTOT, k = idx - n * KTOT;
        float v;
        if (k < DIM) v = lin_w[n * DIM + k];
        else {
            int r = (k - DIM) >> 7, kk = (k - DIM) & 127;
            v = relw[r * DIM * DIM + kk * DIM + n];
        }
        __nv_bfloat16 h = __float2bfloat16(v);
        __nv_bfloat16 l = __float2bfloat16(v - __bfloat162float(h));
        g_wThi[idx] = h;
        g_wTlo[idx] = l;
    }
    for (int i = idx; i < NNODES; i += gridDim.x * blockDim.x) g_cnt2[i] = 0;
}

__global__ void hist_kernel(const int* __restrict__ ei, int E) {
    int i = blockIdx.x * blockDim.x + threadIdx.x;
    if (i < E) atomicAdd(&g_cnt2[ei[E + i]], 1);
}

__global__ void blocksum_kernel() {
    int tid = threadIdx.x, lane = tid & 31, wid = tid >> 5;
    int i = blockIdx.x * 256 + tid;
    int v = (i < NNODES) ? g_cnt2[i] : 0;
    #pragma unroll
    for (int o = 16; o > 0; o >>= 1) v += __shfl_xor_sync(0xffffffffu, v, o);
    __shared__ int ws[8];
    if (lane == 0) ws[wid] = v;
    __syncthreads();
    if (tid == 0) {
        int s = 0;
        #pragma unroll
        for (int j = 0; j < 8; j++) s += ws[j];
        g_part[blockIdx.x] = s;
    }
}

// Each block: reduce partials[j < bid] for its prefix, then scan its 256 counts.
__global__ void scanfinal2_kernel(int E) {
    int tid = threadIdx.x, lane = tid & 31, wid = tid >> 5;
    int bid = blockIdx.x;
    __shared__ int ws[8];
    __shared__ int s_prefix;

    int pv = (tid < bid && tid < NBLK) ? g_part[tid] : 0;
    #pragma unroll
    for (int o = 16; o > 0; o >>= 1) pv += __shfl_xor_sync(0xffffffffu, pv, o);
    if (lane == 0) ws[wid] = pv;
    __syncthreads();
    if (tid == 0) {
        int s = 0;
        #pragma unroll
        for (int j = 0; j < 8; j++) s += ws[j];
        s_prefix = s;
    }
    __syncthreads();
    int prefix = s_prefix;
    __syncthreads();  // ws reused below

    int i = bid * 256 + tid;
    int c = (i < NNODES) ? g_cnt2[i] : 0;
    int v = c;
    #pragma unroll
    for (int o = 1; o < 32; o <<= 1) {
        int n = __shfl_up_sync(0xffffffffu, v, o);
        if (lane >= o) v += n;
    }
    if (lane == 31) ws[wid] = v;
    __syncthreads();
    if (wid == 0 && lane < 8) {
        int w = ws[lane];
        #pragma unroll
        for (int o = 1; o < 8; o <<= 1) {
            int n = __shfl_up_sync(0xffu, w, o);
            if (lane >= o) w += n;
        }
        ws[lane] = w;
    }
    __syncthreads();
    int excl = v - c + (wid > 0 ? ws[wid - 1] : 0) + prefix;
    if (i < NNODES) { g_off[i] = excl; g_woff[i] = excl; }
    if (bid == NBLK - 1 && tid == 0) g_off[NNODES] = E;
}

__global__ void fill_kernel(const int* __restrict__ ei,
                            const int* __restrict__ et, int E) {
    int i = blockIdx.x * blockDim.x + threadIdx.x;
    if (i < E) {
        int d = ei[E + i];
        int r = min(max(et[i], 0), NREL - 1);
        int s = ei[i];
        int pos = atomicAdd(&g_woff[d], 1);
        g_csr[pos] = (r << 16) | s;
    }
}

// ---------------------------------------------------------------------------
// Warp per node: gather-sum per relation, then write the FULL pre-split A
// image rows (seg0 = x[node], seg1..3 = hsum_r * inv) as bf16 hi/lo.
__global__ void __launch_bounds__(256) accum_kernel(const float* __restrict__ x) {
    int warp = threadIdx.x >> 5, lane = threadIdx.x & 31;
    int node = blockIdx.x * 8 + warp;
    if (node >= NNODES) return;
    int beg = g_off[node], end = g_off[node + 1];

    float4 a0 = make_float4(0.f, 0.f, 0.f, 0.f);
    float4 a1 = a0, a2 = a0;
    const float4* x4 = (const float4*)x;

    for (int base = beg; base < end; base += 32) {
        int m = min(32, end - base);
        int p = 0;
        if (lane < m) p = g_csr[base + lane];
        int j = 0;
        for (; j + 4 <= m; j += 4) {
            int p0 = __shfl_sync(0xffffffffu, p, j);
            int p1 = __shfl_sync(0xffffffffu, p, j + 1);
            int p2 = __shfl_sync(0xffffffffu, p, j + 2);
            int p3 = __shfl_sync(0xffffffffu, p, j + 3);
            float4 v0 = x4[(p0 & 0xFFFF) * 32 + lane];
            float4 v1 = x4[(p1 & 0xFFFF) * 32 + lane];
            float4 v2 = x4[(p2 & 0xFFFF) * 32 + lane];
            float4 v3 = x4[(p3 & 0xFFFF) * 32 + lane];
            int r0 = p0 >> 16, r1 = p1 >> 16, r2 = p2 >> 16, r3 = p3 >> 16;
            if (r0 == 0)      { a0.x += v0.x; a0.y += v0.y; a0.z += v0.z; a0.w += v0.w; }
            else if (r0 == 1) { a1.x += v0.x; a1.y += v0.y; a1.z += v0.z; a1.w += v0.w; }
            else              { a2.x += v0.x; a2.y += v0.y; a2.z += v0.z; a2.w += v0.w; }
            if (r1 == 0)      { a0.x += v1.x; a0.y += v1.y; a0.z += v1.z; a0.w += v1.w; }
            else if (r1 == 1) { a1.x += v1.x; a1.y += v1.y; a1.z += v1.z; a1.w += v1.w; }
            else              { a2.x += v1.x; a2.y += v1.y; a2.z += v1.z; a2.w += v1.w; }
            if (r2 == 0)      { a0.x += v2.x; a0.y += v2.y; a0.z += v2.z; a0.w += v2.w; }
            else if (r2 == 1) { a1.x += v2.x; a1.y += v2.y; a1.z += v2.z; a1.w += v2.w; }
            else              { a2.x += v2.x; a2.y += v2.y; a2.z += v2.z; a2.w += v2.w; }
            if (r3 == 0)      { a0.x += v3.x; a0.y += v3.y; a0.z += v3.z; a0.w += v3.w; }
            else if (r3 == 1) { a1.x += v3.x; a1.y += v3.y; a1.z += v3.z; a1.w += v3.w; }
            else              { a2.x += v3.x; a2.y += v3.y; a2.z += v3.z; a2.w += v3.w; }
        }
        for (; j < m; j++) {
            int p0 = __shfl_sync(0xffffffffu, p, j);
            float4 v0 = x4[(p0 & 0xFFFF) * 32 + lane];
            int r0 = p0 >> 16;
            if (r0 == 0)      { a0.x += v0.x; a0.y += v0.y; a0.z += v0.z; a0.w += v0.w; }
            else if (r0 == 1) { a1.x += v0.x; a1.y += v0.y; a1.z += v0.z; a1.w += v0.w; }
            else              { a2.x += v0.x; a2.y += v0.y; a2.z += v0.z; a2.w += v0.w; }
        }
    }

    float inv = (end > beg) ? 1.0f / (float)(end - beg) : 1.0f;
    a0.x *= inv; a0.y *= inv; a0.z *= inv; a0.w *= inv;
    a1.x *= inv; a1.y *= inv; a1.z *= inv; a1.w *= inv;
    a2.x *= inv; a2.y *= inv; a2.z *= inv; a2.w *= inv;

    uint2* Ahi2 = (uint2*)g_Ahi;
    uint2* Alo2 = (uint2*)g_Alo;
    uint2 hi, lo;
    float4 xv = x4[node * 32 + lane];
    split4(xv, hi, lo);
    Ahi2[((size_t)0 * NNODES + node) * 32 + lane] = hi;
    Alo2[((size_t)0 * NNODES + node) * 32 + lane] = lo;
    split4(a0, hi, lo);
    Ahi2[((size_t)1 * NNODES + node) * 32 + lane] = hi;
    Alo2[((size_t)1 * NNODES + node) * 32 + lane] = lo;
    split4(a1, hi, lo);
    Ahi2[((size_t)2 * NNODES + node) * 32 + lane] = hi;
    Alo2[((size_t)2 * NNODES + node) * 32 + lane] = lo;
    split4(a2, hi, lo);
    Ahi2[((size_t)3 * NNODES + node) * 32 + lane] = hi;
    Alo2[((size_t)3 * NNODES + node) * 32 + lane] = lo;
}

// ---------------------------------------------------------------------------
// Fused GEMM (bf16 3-split mma.sync, pure-copy staging) + LayerNorm.
// Warp grid 4(m)x2(n): warp tile M=32, N=64. K chunks of 64.
__global__ __launch_bounds__(256) void final_gemm_mma(
        const float* __restrict__ lin_b,
        const float* __restrict__ gamma,
        const float* __restrict__ beta,
        float* __restrict__ out, int N) {
    extern __shared__ char smem[];
    int tid = threadIdx.x, lane = tid & 31, wid = tid >> 5;
    int wm = wid >> 1, wn = wid & 1;
    int node0 = blockIdx.x * BM;
    int r = lane >> 2, q = lane & 3;

    float acc[2][8][4];
    #pragma unroll
    for (int mi = 0; mi < 2; mi++)
        #pragma unroll
        for (int ni = 0; ni < 8; ni++)
            #pragma unroll
            for (int j = 0; j < 4; j++) acc[mi][ni][j] = 0.f;

    for (int kc = 0; kc < KTOT / 64; kc++) {
        int k0 = kc * 64;
        int seg = k0 >> 7;
        int koff = k0 & 127;

        // stage A: pure int4 copies from the pre-split image
        #pragma unroll
        for (int i = 0; i < 4; i++) {
            int idx = i * 256 + tid;
            int row = idx >> 3, g = idx & 7;
            int node = node0 + row;
            int4 vh = make_int4(0, 0, 0, 0), vl = vh;
            if (node < N) {
                size_t base = ((size_t)seg * NNODES + node) * DIM + koff + g * 8;
                vh = *(const int4*)(g_Ahi + base);
                vl = *(const int4*)(g_Alo + base);
            }
            *(int4*)(smem + OFF_AHI + row * ROWB + g * 16) = vh;
            *(int4*)(smem + OFF_ALO + row * ROWB + g * 16) = vl;
        }
        // stage B
        #pragma unroll
        for (int i = 0; i < 4; i++) {
            int idx = i * 256 + tid;
            int n = idx >> 3, g = idx & 7;
            *(int4*)(smem + OFF_BHI + n * ROWB + g * 16) =
                *(const int4*)(g_wThi + (size_t)n * KTOT + k0 + g * 8);
            *(int4*)(smem + OFF_BLO + n * ROWB + g * 16) =
                *(const int4*)(g_wTlo + (size_t)n * KTOT + k0 + g * 8);
        }
        __syncthreads();

        #pragma unroll
        for (int k16 = 0; k16 < 4; k16++) {
            int kb = k16 * 16 + q * 2;
            uint32_t ah[2][4], al[2][4];
            #pragma unroll
            for (int mi = 0; mi < 2; mi++) {
                int rb = wm * 32 + mi * 16 + r;
                const char* ph = smem + OFF_AHI;
                const char* pl = smem + OFF_ALO;
                ah[mi][0] = *(const uint32_t*)(ph + rb * ROWB + kb * 2);
                ah[mi][1] = *(const uint32_t*)(ph + (rb + 8) * ROWB + kb * 2);
                ah[mi][2] = *(const uint32_t*)(ph + rb * ROWB + (kb + 8) * 2);
                ah[mi][3] = *(const uint32_t*)(ph + (rb + 8) * ROWB + (kb + 8) * 2);
                al[mi][0] = *(const uint32_t*)(pl + rb * ROWB + kb * 2);
                al[mi][1] = *(const uint32_t*)(pl + (rb + 8) * ROWB + kb * 2);
                al[mi][2] = *(const uint32_t*)(pl + rb * ROWB + (kb + 8) * 2);
                al[mi][3] = *(const uint32_t*)(pl + (rb + 8) * ROWB + (kb + 8) * 2);
            }
            uint32_t bh[8][2], bl[8][2];
            #pragma unroll
            for (int ni = 0; ni < 8; ni++) {
                int n = wn * 64 + ni * 8 + r;
                bh[ni][0] = *(const uint32_t*)(smem + OFF_BHI + n * ROWB + kb * 2);
                bh[ni][1] = *(const uint32_t*)(smem + OFF_BHI + n * ROWB + (kb + 8) * 2);
                bl[ni][0] = *(const uint32_t*)(smem + OFF_BLO + n * ROWB + kb * 2);
                bl[ni][1] = *(const uint32_t*)(smem + OFF_BLO + n * ROWB + (kb + 8) * 2);
            }
            #pragma unroll
            for (int mi = 0; mi < 2; mi++)
                #pragma unroll
                for (int ni = 0; ni < 8; ni++) {
                    MMA_BF16(acc[mi][ni], ah[mi], bh[ni]);
                    MMA_BF16(acc[mi][ni], ah[mi], bl[ni]);
                    MMA_BF16(acc[mi][ni], al[mi], bh[ni]);
                }
        }
        __syncthreads();
    }

    // ---- bias + LayerNorm (cross-warp partials in smem) ----
    float* sS = (float*)smem;          // [2][128]
    float* sQ = ((float*)smem) + 256;  // [2][128]

    #pragma unroll
    for (int mi = 0; mi < 2; mi++) {
        #pragma unroll
        for (int ni = 0; ni < 8; ni++) {
            int col = wn * 64 + ni * 8 + q * 2;
            float2 bb = *(const float2*)(lin_b + col);
            acc[mi][ni][0] += bb.x; acc[mi][ni][1] += bb.y;
            acc[mi][ni][2] += bb.x; acc[mi][ni][3] += bb.y;
        }
        float sa = 0.f, qa = 0.f, sb = 0.f, qb = 0.f;
        #pragma unroll
        for (int ni = 0; ni < 8; ni++) {
            float c0 = acc[mi][ni][0], c1 = acc[mi][ni][1];
            float c2 = acc[mi][ni][2], c3 = acc[mi][ni][3];
            sa += c0 + c1; qa += c0 * c0 + c1 * c1;
            sb += c2 + c3; qb += c2 * c2 + c3 * c3;
        }
        #pragma unroll
        for (int o = 1; o <= 2; o <<= 1) {
            sa += __shfl_xor_sync(0xffffffffu, sa, o);
            qa += __shfl_xor_sync(0xffffffffu, qa, o);
            sb += __shfl_xor_sync(0xffffffffu, sb, o);
            qb += __shfl_xor_sync(0xffffffffu, qb, o);
        }
        if (q == 0) {
            int ra = wm * 32 + mi * 16 + r;
            sS[wn * 128 + ra] = sa;     sQ[wn * 128 + ra] = qa;
            sS[wn * 128 + ra + 8] = sb; sQ[wn * 128 + ra + 8] = qb;
        }
    }
    __syncthreads();

    #pragma unroll
    for (int mi = 0; mi < 2; mi++) {
        int ra = wm * 32 + mi * 16 + r;
        float s_a = sS[ra] + sS[128 + ra];
        float q_a = sQ[ra] + sQ[128 + ra];
        float s_b = sS[ra + 8] + sS[128 + ra + 8];
        float q_b = sQ[ra + 8] + sQ[128 + ra + 8];
        float mu_a = s_a * (1.0f / DIM);
        float mu_b = s_b * (1.0f / DIM);
        float rs_a = rsqrtf(fmaxf(q_a * (1.0f / DIM) - mu_a * mu_a, 0.f) + 1e-5f);
        float rs_b = rsqrtf(fmaxf(q_b * (1.0f / DIM) - mu_b * mu_b, 0.f) + 1e-5f);
        int na = node0 + ra, nb = na + 8;
        #pragma unroll
        for (int ni = 0; ni < 8; ni++) {
            int col = wn * 64 + ni * 8 + q * 2;
            float2 gm = *(const float2*)(gamma + col);
            float2 be = *(const float2*)(beta + col);
            if (na < N) {
                float2 o0;
                o0.x = fmaf(gm.x * (acc[mi][ni][0] - mu_a), rs_a, be.x);
                o0.y = fmaf(gm.y * (acc[mi][ni][1] - mu_a), rs_a, be.y);
                *(float2*)(out + (size_t)na * DIM + col) = o0;
            }
            if (nb < N) {
                float2 o1;
                o1.x = fmaf(gm.x * (acc[mi][ni][2] - mu_b), rs_b, be.x);
                o1.y = fmaf(gm.y * (acc[mi][ni][3] - mu_b), rs_b, be.y);
                *(float2*)(out + (size_t)nb * DIM + col) = o1;
            }
        }
    }
}

// ---------------------------------------------------------------------------
extern "C" void kernel_launch(void* const* d_in, const int* in_sizes, int n_in,
                              void* d_out, int out_size) {
    const float* x     = (const float*)d_in[0];
    const int*   ei    = (const int*)d_in[1];
    const int*   et    = (const int*)d_in[2];
    const float* relw  = (const float*)d_in[3];
    const float* lin_w = (const float*)d_in[4];
    const float* lin_b = (const float*)d_in[5];
    const float* gamma = (const float*)d_in[6];
    const float* beta  = (const float*)d_in[7];
    float* out = (float*)d_out;

    int N = in_sizes[0] / DIM;
    int E = in_sizes[2];

    cudaFuncSetAttribute(final_gemm_mma,
                         cudaFuncAttributeMaxDynamicSharedMemorySize, SMEM_TOT);

    prep_kernel<<<(DIM * KTOT + 255) / 256, 256>>>(lin_w, relw);
    hist_kernel<<<(E + 255) / 256, 256>>>(ei, E);
    blocksum_kernel<<<NBLK, 256>>>();
    scanfinal2_kernel<<<NBLK, 256>>>(E);
    fill_kernel<<<(E + 255) / 256, 256>>>(ei, et, E);
    accum_kernel<<<(NNODES + 7) / 8, 256>>>(x);
    final_gemm_mma<<<(N + BM - 1) / BM, 256, SMEM_TOT>>>(lin_b, gamma, beta, out, N);
}